// round 10
// baseline (speedup 1.0000x reference)
#include <cuda_runtime.h>

#define N_FWD  8192
#define T_LEN  4096
#define PAD    2048
#define B_MAX  64
#define FROW   4104           // g_F row stride in float2 (4097 rounded up)
#define FTH    1024
#define ITH    512

// Scalar padding (fwd kernel, two scalar arrays)
#define PHYS(i) ((i) + ((i) >> 3))
#define FWD_PAD 9216          // PHYS(8191)=9214 -> 9216
// Complex padding (cwt kernel, interleaved float2 array)
#define CPAD(i) ((i) + ((i) >> 3))
#define INV_CPAD 4608         // CPAD(4095)=4606 -> 4608 float2

#define LOG_OFF (-9.0109133472792881f)   // -ln(8192): folds 1/n into the log

__device__ float2 g_F[B_MAX * FROW];   // half spectra F[k], k in [0,4096]

// ---------------------------------------------------------------------------
// In-register radix-8 butterfly. FWD: e^{-2pi i jr/8}; INV: e^{+...}.
// ---------------------------------------------------------------------------
template<bool FWD>
__device__ __forceinline__ void bfly8(float* xr, float* xi)
{
    const float C = 0.70710678118654752440f;
    float t0r=xr[0]+xr[4], t0i=xi[0]+xi[4];
    float t4r=xr[0]-xr[4], t4i=xi[0]-xi[4];
    float t1r=xr[1]+xr[5], t1i=xi[1]+xi[5];
    float t5r=xr[1]-xr[5], t5i=xi[1]-xi[5];
    float t2r=xr[2]+xr[6], t2i=xi[2]+xi[6];
    float t6r=xr[2]-xr[6], t6i=xi[2]-xi[6];
    float t3r=xr[3]+xr[7], t3i=xi[3]+xi[7];
    float t7r=xr[3]-xr[7], t7i=xi[3]-xi[7];

    float u0r=t0r+t2r, u0i=t0i+t2i;
    float u1r=t0r-t2r, u1i=t0i-t2i;
    float u2r=t1r+t3r, u2i=t1i+t3i;
    float u3r=t1r-t3r, u3i=t1i-t3i;
    xr[0]=u0r+u2r; xi[0]=u0i+u2i;
    xr[4]=u0r-u2r; xi[4]=u0i-u2i;
    if (FWD) { xr[2]=u1r+u3i; xi[2]=u1i-u3r; xr[6]=u1r-u3i; xi[6]=u1i+u3r; }
    else     { xr[2]=u1r-u3i; xi[2]=u1i+u3r; xr[6]=u1r+u3i; xi[6]=u1i-u3r; }

    float a5r,a5i,a6r,a6i,a7r,a7i;
    if (FWD) {
        a5r =  C*(t5r+t5i);  a5i =  C*(t5i-t5r);
        a6r =  t6i;          a6i = -t6r;
        a7r =  C*(t7i-t7r);  a7i = -C*(t7r+t7i);
    } else {
        a5r =  C*(t5r-t5i);  a5i =  C*(t5r+t5i);
        a6r = -t6i;          a6i =  t6r;
        a7r = -C*(t7r+t7i);  a7i =  C*(t7r-t7i);
    }
    float v0r=t4r+a6r, v0i=t4i+a6i;
    float v1r=t4r-a6r, v1i=t4i-a6i;
    float v2r=a5r+a7r, v2i=a5i+a7i;
    float v3r=a5r-a7r, v3i=a5i-a7i;
    xr[1]=v0r+v2r; xi[1]=v0i+v2i;
    xr[5]=v0r-v2r; xi[5]=v0i-v2i;
    if (FWD) { xr[3]=v1r+v3i; xi[3]=v1i-v3r; xr[7]=v1r-v3i; xi[7]=v1i+v3r; }
    else     { xr[3]=v1r-v3i; xi[3]=v1i+v3r; xr[7]=v1r+v3i; xi[7]=v1i-v3r; }
}

// ---------------------------------------------------------------------------
// Twiddle powers by repeated squaring (register-only, depth 3).
// ---------------------------------------------------------------------------

// Forward store (scalar arrays, fwd kernel only).
__device__ __forceinline__ void store8(float* dr, float* di,
                                       const float* xr, const float* xi,
                                       int o, int m, float w1r, float w1i)
{
    float w2r = w1r*w1r - w1i*w1i, w2i = 2.0f*w1r*w1i;
    float w3r = w2r*w1r - w2i*w1i, w3i = w2r*w1i + w2i*w1r;
    float w4r = w2r*w2r - w2i*w2i, w4i = 2.0f*w2r*w2i;
    float w5r = w4r*w1r - w4i*w1i, w5i = w4r*w1i + w4i*w1r;
    float w6r = w3r*w3r - w3i*w3i, w6i = 2.0f*w3r*w3i;
    float w7r = w4r*w3r - w4i*w3i, w7i = w4r*w3i + w4i*w3r;

    int p;
    p = PHYS(o);         dr[p] = xr[0];                     di[p] = xi[0];
    p = PHYS(o + m);     dr[p] = xr[1]*w1r - xi[1]*w1i;     di[p] = xr[1]*w1i + xi[1]*w1r;
    p = PHYS(o + 2*m);   dr[p] = xr[2]*w2r - xi[2]*w2i;     di[p] = xr[2]*w2i + xi[2]*w2r;
    p = PHYS(o + 3*m);   dr[p] = xr[3]*w3r - xi[3]*w3i;     di[p] = xr[3]*w3i + xi[3]*w3r;
    p = PHYS(o + 4*m);   dr[p] = xr[4]*w4r - xi[4]*w4i;     di[p] = xr[4]*w4i + xi[4]*w4r;
    p = PHYS(o + 5*m);   dr[p] = xr[5]*w5r - xi[5]*w5i;     di[p] = xr[5]*w5i + xi[5]*w5r;
    p = PHYS(o + 6*m);   dr[p] = xr[6]*w6r - xi[6]*w6i;     di[p] = xr[6]*w6i + xi[6]*w6r;
    p = PHYS(o + 7*m);   dr[p] = xr[7]*w7r - xi[7]*w7i;     di[p] = xr[7]*w7i + xi[7]*w7r;
}

// Inverse store: interleaved complex float2 array (STS.64, conflict-free).
__device__ __forceinline__ void store8c(float2* d,
                                        const float* xr, const float* xi,
                                        int o, int m, float w1r, float w1i)
{
    float w2r = w1r*w1r - w1i*w1i, w2i = 2.0f*w1r*w1i;
    float w3r = w2r*w1r - w2i*w1i, w3i = w2r*w1i + w2i*w1r;
    float w4r = w2r*w2r - w2i*w2i, w4i = 2.0f*w2r*w2i;
    float w5r = w4r*w1r - w4i*w1i, w5i = w4r*w1i + w4i*w1r;
    float w6r = w3r*w3r - w3i*w3i, w6i = 2.0f*w3r*w3i;
    float w7r = w4r*w3r - w4i*w3i, w7i = w4r*w3i + w4i*w3r;

    d[CPAD(o)]       = make_float2(xr[0],                  xi[0]);
    d[CPAD(o + m)]   = make_float2(xr[1]*w1r - xi[1]*w1i,  xr[1]*w1i + xi[1]*w1r);
    d[CPAD(o + 2*m)] = make_float2(xr[2]*w2r - xi[2]*w2i,  xr[2]*w2i + xi[2]*w2r);
    d[CPAD(o + 3*m)] = make_float2(xr[3]*w3r - xi[3]*w3i,  xr[3]*w3i + xi[3]*w3r);
    d[CPAD(o + 4*m)] = make_float2(xr[4]*w4r - xi[4]*w4i,  xr[4]*w4i + xi[4]*w4r);
    d[CPAD(o + 5*m)] = make_float2(xr[5]*w5r - xi[5]*w5i,  xr[5]*w5i + xi[5]*w5r);
    d[CPAD(o + 6*m)] = make_float2(xr[6]*w6r - xi[6]*w6i,  xr[6]*w6i + xi[6]*w6r);
    d[CPAD(o + 7*m)] = make_float2(xr[7]*w7r - xi[7]*w7i,  xr[7]*w7i + xi[7]*w7r);
}

// Stage-1, pass-1 store: twiddles c_r = A * w1^r (A folded rotation factor).
// 9 independent complex muls, depth 3.
__device__ __forceinline__ void store8c_A(float2* d,
                                          const float* xr, const float* xi,
                                          int o,
                                          float Ar_, float Ai_,
                                          float w1r, float w1i)
{
    float w2r = w1r*w1r - w1i*w1i, w2i = 2.0f*w1r*w1i;
    float w4r = w2r*w2r - w2i*w2i, w4i = 2.0f*w2r*w2i;
    float c0r = Ar_,                c0i = Ai_;
    float c1r = c0r*w1r - c0i*w1i,  c1i = c0r*w1i + c0i*w1r;
    float c2r = c0r*w2r - c0i*w2i,  c2i = c0r*w2i + c0i*w2r;
    float c3r = c1r*w2r - c1i*w2i,  c3i = c1r*w2i + c1i*w2r;
    float c4r = c0r*w4r - c0i*w4i,  c4i = c0r*w4i + c0i*w4r;
    float c5r = c1r*w4r - c1i*w4i,  c5i = c1r*w4i + c1i*w4r;
    float c6r = c2r*w4r - c2i*w4i,  c6i = c2r*w4i + c2i*w4r;
    float c7r = c3r*w4r - c3i*w4i,  c7i = c3r*w4i + c3i*w4r;

    d[CPAD(o)]     = make_float2(xr[0]*c0r - xi[0]*c0i,  xr[0]*c0i + xi[0]*c0r);
    d[CPAD(o + 1)] = make_float2(xr[1]*c1r - xi[1]*c1i,  xr[1]*c1i + xi[1]*c1r);
    d[CPAD(o + 2)] = make_float2(xr[2]*c2r - xi[2]*c2i,  xr[2]*c2i + xi[2]*c2r);
    d[CPAD(o + 3)] = make_float2(xr[3]*c3r - xi[3]*c3i,  xr[3]*c3i + xi[3]*c3r);
    d[CPAD(o + 4)] = make_float2(xr[4]*c4r - xi[4]*c4i,  xr[4]*c4i + xi[4]*c4r);
    d[CPAD(o + 5)] = make_float2(xr[5]*c5r - xi[5]*c5i,  xr[5]*c5i + xi[5]*c5r);
    d[CPAD(o + 6)] = make_float2(xr[6]*c6r - xi[6]*c6i,  xr[6]*c6i + xi[6]*c6r);
    d[CPAD(o + 7)] = make_float2(xr[7]*c7r - xi[7]*c7i,  xr[7]*c7i + xi[7]*c7r);
}

// ===========================================================================
// Forward 8192-pt FFT (radix-8 x4 + radix-2), one CTA per batch row.
// Twiddles via sincospif (MUFU) — no table, no init kernel.
// ===========================================================================
__device__ __forceinline__ void fwd_stage(const float* sr, const float* si,
                                          float* dr, float* di, int m, int tid)
{
    float xr[8], xi[8];
    #pragma unroll
    for (int q = 0; q < 8; ++q) {
        int p = PHYS(tid + q * 1024);
        xr[q] = sr[p]; xi[q] = si[p];
    }
    bfly8<true>(xr, xi);
    int k = tid & (m - 1), jm = tid - k;
    float ss, cc;                                  // e^{-2 pi i jm/8192}
    sincospif((float)jm * (1.0f / 4096.0f), &ss, &cc);
    store8(dr, di, xr, xi, 8 * jm + k, m, cc, -ss);
}

extern __shared__ float sm_[];

__global__ void __launch_bounds__(FTH, 1)
fwd_fft_kernel(const float* __restrict__ in)
{
    float* Ar = sm_;
    float* Ai = sm_ + FWD_PAD;
    float* Br = sm_ + 2 * FWD_PAD;
    float* Bi = sm_ + 3 * FWD_PAD;

    const int b = blockIdx.x, tid = threadIdx.x;
    const float* x = in + b * T_LEN;

    {
        float xr[8], xi[8];
        #pragma unroll
        for (int q = 0; q < 8; ++q) {
            int i = tid + q * 1024;
            int src;
            if (i < PAD)              src = PAD - 1 - i;
            else if (i < PAD + T_LEN) src = i - PAD;
            else                      src = (2 * T_LEN + PAD - 1) - i;
            xr[q] = x[src]; xi[q] = 0.0f;
        }
        bfly8<true>(xr, xi);
        float ss, cc;
        sincospif((float)tid * (1.0f / 4096.0f), &ss, &cc);
        store8(Ar, Ai, xr, xi, 8 * tid, 1, cc, -ss);
    }
    __syncthreads();
    fwd_stage(Ar, Ai, Br, Bi,   8, tid); __syncthreads();
    fwd_stage(Br, Bi, Ar, Ai,  64, tid); __syncthreads();
    fwd_stage(Ar, Ai, Br, Bi, 512, tid); __syncthreads();

    float2* Fo = g_F + b * FROW;
    #pragma unroll
    for (int q = 0; q < 4; ++q) {
        int k = tid + q * 1024;
        float ur = Br[PHYS(k)],        ui = Bi[PHYS(k)];
        float vr = Br[PHYS(k + 4096)], vi = Bi[PHYS(k + 4096)];
        Fo[k] = make_float2(ur + vr, ui + vi);
        if (k == 0) Fo[4096] = make_float2(ur - vr, ui - vi);
    }
}

// ===========================================================================
// CWT inverse kernel: one CTA per (b,s). Two sequential 4096-pt inverse
// radix-8 Stockham FFTs (even / odd samples of the 8192-pt IFFT of the
// half-spectrum G = F*wft; 1/n folded into the log constant).
// All twiddles computed via sincospif; pass-1 rotation e^{+2pi i k/8192}
// factorized into constant B(q)=e^{i pi q/8} input muls and a per-thread A
// folded into the stage-1 output twiddles. No twiddle tables anywhere.
// ===========================================================================
__device__ __forceinline__ void inv_stage(const float2* s, float2* d,
                                          int m, int tid)
{
    float xr[8], xi[8];
    #pragma unroll
    for (int q = 0; q < 8; ++q) {
        float2 v = s[CPAD(tid + q * 512)];
        xr[q] = v.x; xi[q] = v.y;
    }
    bfly8<false>(xr, xi);
    int k = tid & (m - 1), jm = tid - k;
    float ss, cc;                                  // e^{+2 pi i jm/4096}
    sincospif((float)jm * (1.0f / 2048.0f), &ss, &cc);
    store8c(d, xr, xi, 8 * jm + k, m, cc, ss);
}

__global__ void __launch_bounds__(ITH, 2)
cwt_kernel(const float* __restrict__ wft, float* __restrict__ out, int S)
{
    float2* A  = (float2*)sm_;
    float2* Bb = A + INV_CPAD;

    const int tid = threadIdx.x;
    const int s = blockIdx.x % S, b = blockIdx.x / S;
    const float2* __restrict__ F = g_F + b * FROW;
    const float*  __restrict__ w = wft + (size_t)s * N_FWD;

    float2 fn = F[4096];
    float  gn = w[4096];
    float  nyr = fn.x * gn, nyi = fn.y * gn;

    float ev[4];     // pass-0 log values (same thread & columns in pass 1)

    // B(q) = e^{+i pi q/8} constants for the pass-1 rotation
    const float C8 = 0.92387953251128675613f;  // cos(pi/8)
    const float S8 = 0.38268343236508977173f;  // sin(pi/8)
    const float CQ = 0.70710678118654752440f;  // cos(pi/4)
    const float Bqr[8] = {1.0f,  C8,  CQ,  S8, 0.0f, -S8, -CQ, -C8};
    const float Bqi[8] = {0.0f,  S8,  CQ,  C8, 1.0f,  C8,  CQ,  S8};

    #pragma unroll
    for (int pass = 0; pass < 2; ++pass) {
        float xr[8], xi[8];

        // stage m=1 fused with global load + spectrum multiply.
        // Pass 1 additionally multiplies input q by B(q) (constants).
        #pragma unroll
        for (int q = 0; q < 8; ++q) {
            int k = tid + q * 512;
            float2 f = F[k];
            float  g = w[k];
            float vr = f.x * g, vi = f.y * g;
            if (pass) {
                float br = Bqr[q], bi = Bqi[q];
                float r2 = vr * br - vi * bi;
                float i2 = vr * bi + vi * br;
                vr = r2; vi = i2;
            }
            xr[q] = vr; xi[q] = vi;
        }
        bfly8<false>(xr, xi);
        {
            float sA, cA;                          // A = e^{+2 pi i tid/8192}
            sincospif((float)tid * (1.0f / 4096.0f), &sA, &cA);
            float w1r = cA * cA - sA * sA;         // w1 = A^2 = e^{+2 pi i tid/4096}
            float w1i = 2.0f * cA * sA;
            if (pass == 0)
                store8c(A, xr, xi, 8 * tid, 1, w1r, w1i);
            else
                store8c_A(A, xr, xi, 8 * tid, cA, sA, w1r, w1i);
        }
        __syncthreads();
        inv_stage(A, Bb,  8, tid); __syncthreads();
        inv_stage(Bb, A, 64, tid); __syncthreads();

        // final stage m=512 (jm=0, W=1) fused with Nyquist + log|.| + store.
        // Thread tid produces u = tid + 512 r; needed u in [1024,3072) -> r=2..5.
        #pragma unroll
        for (int q = 0; q < 8; ++q) {
            float2 v = A[CPAD(tid + q * 512)];
            xr[q] = v.x; xi[q] = v.y;
        }
        bfly8<false>(xr, xi);

        float nr = pass ? -nyr : nyr;
        float ni = pass ? -nyi : nyi;
        if (pass == 0) {
            #pragma unroll
            for (int r = 2; r <= 5; ++r) {
                float a = xr[r] + nr, bb = xi[r] + ni;
                ev[r - 2] = fmaf(0.5f, __logf(a * a + bb * bb), LOG_OFF);
            }
        } else {
            float2* o2 = (float2*)(out + (size_t)blockIdx.x * T_LEN);
            #pragma unroll
            for (int r = 2; r <= 5; ++r) {
                float a = xr[r] + nr, bb = xi[r] + ni;
                float lg = fmaf(0.5f, __logf(a * a + bb * bb), LOG_OFF);
                o2[tid + 512 * (r - 2)] = make_float2(ev[r - 2], lg);
            }
        }
        __syncthreads();
    }
}

// ---------------------------------------------------------------------------
extern "C" void kernel_launch(void* const* d_in, const int* in_sizes, int n_in,
                              void* d_out, int out_size)
{
    const float* in  = (const float*)d_in[0];
    const float* wft = (const float*)d_in[1];
    float* out = (float*)d_out;

    const int B = in_sizes[0] / T_LEN;     // 64
    const int S = in_sizes[1] / N_FWD;     // 75

    const int fwd_smem = 4 * FWD_PAD * sizeof(float);      // 147456 B
    const int cwt_smem = 2 * INV_CPAD * sizeof(float2);    //  73728 B
    cudaFuncSetAttribute(fwd_fft_kernel,
                         cudaFuncAttributeMaxDynamicSharedMemorySize, fwd_smem);
    cudaFuncSetAttribute(cwt_kernel,
                         cudaFuncAttributeMaxDynamicSharedMemorySize, cwt_smem);

    fwd_fft_kernel<<<B, FTH, fwd_smem>>>(in);
    cwt_kernel<<<B * S, ITH, cwt_smem>>>(wft, out, S);
}

// round 11
// speedup vs baseline: 1.6236x; 1.6236x over previous
#include <cuda_runtime.h>

#define N_FWD  8192
#define T_LEN  4096
#define PAD    2048
#define B_MAX  64
#define FROW   4104           // g_F row stride in float2 (4097 rounded up)
#define FTH    1024
#define ITH    256

// Scalar padding (fwd kernel, two scalar arrays)
#define PHYS(i) ((i) + ((i) >> 3))
#define FWD_PAD 9216          // PHYS(8191)=9214 -> 9216
// Complex padding (cwt kernel, interleaved float2, radix-16 stride pattern)
#define P16(i)  ((i) + ((i) >> 4))
#define INV_CP  4352          // P16(4095)=4350 -> 4352 float2

#define LOG_OFF (-9.0109133472792881f)   // -ln(8192): folds 1/n into the log

__device__ float2 g_F[B_MAX * FROW];   // half spectra F[k], k in [0,4096]

__device__ __forceinline__ void cmulf(float& zr, float& zi,
                                      float ar, float ai, float br, float bi) {
    zr = ar * br - ai * bi;
    zi = ar * bi + ai * br;
}

// ===========================================================================
// FORWARD kernel (radix-8, unchanged from the R9/R10 structure)
// ===========================================================================
template<bool FWD>
__device__ __forceinline__ void bfly8(float* xr, float* xi)
{
    const float C = 0.70710678118654752440f;
    float t0r=xr[0]+xr[4], t0i=xi[0]+xi[4];
    float t4r=xr[0]-xr[4], t4i=xi[0]-xi[4];
    float t1r=xr[1]+xr[5], t1i=xi[1]+xi[5];
    float t5r=xr[1]-xr[5], t5i=xi[1]-xi[5];
    float t2r=xr[2]+xr[6], t2i=xi[2]+xi[6];
    float t6r=xr[2]-xr[6], t6i=xi[2]-xi[6];
    float t3r=xr[3]+xr[7], t3i=xi[3]+xi[7];
    float t7r=xr[3]-xr[7], t7i=xi[3]-xi[7];

    float u0r=t0r+t2r, u0i=t0i+t2i;
    float u1r=t0r-t2r, u1i=t0i-t2i;
    float u2r=t1r+t3r, u2i=t1i+t3i;
    float u3r=t1r-t3r, u3i=t1i-t3i;
    xr[0]=u0r+u2r; xi[0]=u0i+u2i;
    xr[4]=u0r-u2r; xi[4]=u0i-u2i;
    if (FWD) { xr[2]=u1r+u3i; xi[2]=u1i-u3r; xr[6]=u1r-u3i; xi[6]=u1i+u3r; }
    else     { xr[2]=u1r-u3i; xi[2]=u1i+u3r; xr[6]=u1r+u3i; xi[6]=u1i-u3r; }

    float a5r,a5i,a6r,a6i,a7r,a7i;
    if (FWD) {
        a5r =  C*(t5r+t5i);  a5i =  C*(t5i-t5r);
        a6r =  t6i;          a6i = -t6r;
        a7r =  C*(t7i-t7r);  a7i = -C*(t7r+t7i);
    } else {
        a5r =  C*(t5r-t5i);  a5i =  C*(t5r+t5i);
        a6r = -t6i;          a6i =  t6r;
        a7r = -C*(t7r+t7i);  a7i =  C*(t7r-t7i);
    }
    float v0r=t4r+a6r, v0i=t4i+a6i;
    float v1r=t4r-a6r, v1i=t4i-a6i;
    float v2r=a5r+a7r, v2i=a5i+a7i;
    float v3r=a5r-a7r, v3i=a5i-a7i;
    xr[1]=v0r+v2r; xi[1]=v0i+v2i;
    xr[5]=v0r-v2r; xi[5]=v0i-v2i;
    if (FWD) { xr[3]=v1r+v3i; xi[3]=v1i-v3r; xr[7]=v1r-v3i; xi[7]=v1i+v3r; }
    else     { xr[3]=v1r-v3i; xi[3]=v1i+v3r; xr[7]=v1r+v3i; xi[7]=v1i-v3r; }
}

__device__ __forceinline__ void store8(float* dr, float* di,
                                       const float* xr, const float* xi,
                                       int o, int m, float w1r, float w1i)
{
    float w2r = w1r*w1r - w1i*w1i, w2i = 2.0f*w1r*w1i;
    float w3r = w2r*w1r - w2i*w1i, w3i = w2r*w1i + w2i*w1r;
    float w4r = w2r*w2r - w2i*w2i, w4i = 2.0f*w2r*w2i;
    float w5r = w4r*w1r - w4i*w1i, w5i = w4r*w1i + w4i*w1r;
    float w6r = w3r*w3r - w3i*w3i, w6i = 2.0f*w3r*w3i;
    float w7r = w4r*w3r - w4i*w3i, w7i = w4r*w3i + w4i*w3r;

    int p;
    p = PHYS(o);         dr[p] = xr[0];                     di[p] = xi[0];
    p = PHYS(o + m);     dr[p] = xr[1]*w1r - xi[1]*w1i;     di[p] = xr[1]*w1i + xi[1]*w1r;
    p = PHYS(o + 2*m);   dr[p] = xr[2]*w2r - xi[2]*w2i;     di[p] = xr[2]*w2i + xi[2]*w2r;
    p = PHYS(o + 3*m);   dr[p] = xr[3]*w3r - xi[3]*w3i;     di[p] = xr[3]*w3i + xi[3]*w3r;
    p = PHYS(o + 4*m);   dr[p] = xr[4]*w4r - xi[4]*w4i;     di[p] = xr[4]*w4i + xi[4]*w4r;
    p = PHYS(o + 5*m);   dr[p] = xr[5]*w5r - xi[5]*w5i;     di[p] = xr[5]*w5i + xi[5]*w5r;
    p = PHYS(o + 6*m);   dr[p] = xr[6]*w6r - xi[6]*w6i;     di[p] = xr[6]*w6i + xi[6]*w6r;
    p = PHYS(o + 7*m);   dr[p] = xr[7]*w7r - xi[7]*w7i;     di[p] = xr[7]*w7i + xi[7]*w7r;
}

__device__ __forceinline__ void fwd_stage(const float* sr, const float* si,
                                          float* dr, float* di, int m, int tid)
{
    float xr[8], xi[8];
    #pragma unroll
    for (int q = 0; q < 8; ++q) {
        int p = PHYS(tid + q * 1024);
        xr[q] = sr[p]; xi[q] = si[p];
    }
    bfly8<true>(xr, xi);
    int k = tid & (m - 1), jm = tid - k;
    float ss, cc;                                  // e^{-2 pi i jm/8192}
    sincospif((float)jm * (1.0f / 4096.0f), &ss, &cc);
    store8(dr, di, xr, xi, 8 * jm + k, m, cc, -ss);
}

extern __shared__ float sm_[];

__global__ void __launch_bounds__(FTH, 1)
fwd_fft_kernel(const float* __restrict__ in)
{
    float* Ar = sm_;
    float* Ai = sm_ + FWD_PAD;
    float* Br = sm_ + 2 * FWD_PAD;
    float* Bi = sm_ + 3 * FWD_PAD;

    const int b = blockIdx.x, tid = threadIdx.x;
    const float* x = in + b * T_LEN;

    {
        float xr[8], xi[8];
        #pragma unroll
        for (int q = 0; q < 8; ++q) {
            int i = tid + q * 1024;
            int src;
            if (i < PAD)              src = PAD - 1 - i;
            else if (i < PAD + T_LEN) src = i - PAD;
            else                      src = (2 * T_LEN + PAD - 1) - i;
            xr[q] = x[src]; xi[q] = 0.0f;
        }
        bfly8<true>(xr, xi);
        float ss, cc;
        sincospif((float)tid * (1.0f / 4096.0f), &ss, &cc);
        store8(Ar, Ai, xr, xi, 8 * tid, 1, cc, -ss);
    }
    __syncthreads();
    fwd_stage(Ar, Ai, Br, Bi,   8, tid); __syncthreads();
    fwd_stage(Br, Bi, Ar, Ai,  64, tid); __syncthreads();
    fwd_stage(Ar, Ai, Br, Bi, 512, tid); __syncthreads();

    float2* Fo = g_F + b * FROW;
    #pragma unroll
    for (int q = 0; q < 4; ++q) {
        int k = tid + q * 1024;
        float ur = Br[PHYS(k)],        ui = Bi[PHYS(k)];
        float vr = Br[PHYS(k + 4096)], vi = Bi[PHYS(k + 4096)];
        Fo[k] = make_float2(ur + vr, ui + vi);
        if (k == 0) Fo[4096] = make_float2(ur - vr, ui - vi);
    }
}

// ===========================================================================
// CWT inverse kernel: radix-16 Stockham (4096 = 16^3, 256 threads).
// Only 2 smem round trips per pass (stage1 fused with the global load,
// stage3 fused with the log epilogue). Twiddles all register-computed from
// two hoisted sincospif calls via depth<=4 multiplication trees.
// ===========================================================================

// Inverse 16-pt DFT: input index j in xr/xi, output index r in yr/yi.
// (Structure identical to the correctness-proven R4 butterfly.)
__device__ __forceinline__ void bfly16_inv(const float* xr, const float* xi,
                                           float* yr, float* yi)
{
    float sr[16], si[16];
    #pragma unroll
    for (int b = 0; b < 4; ++b) {
        float p0r=xr[b],    p0i=xi[b];
        float p1r=xr[b+4],  p1i=xi[b+4];
        float p2r=xr[b+8],  p2i=xi[b+8];
        float p3r=xr[b+12], p3i=xi[b+12];
        float u0r=p0r+p2r, u0i=p0i+p2i;
        float u1r=p0r-p2r, u1i=p0i-p2i;
        float u2r=p1r+p3r, u2i=p1i+p3i;
        float u3r=p1r-p3r, u3i=p1i-p3i;
        sr[b]    = u0r+u2r; si[b]    = u0i+u2i;
        sr[b+4]  = u1r-u3i; si[b+4]  = u1i+u3r;   // * (+i)
        sr[b+8]  = u0r-u2r; si[b+8]  = u0i-u2i;
        sr[b+12] = u1r+u3i; si[b+12] = u1i-u3r;   // * (-i)
    }

    const float CQ = 0.70710678118654752440f;
    const float C8 = 0.92387953251128675613f;
    const float S8 = 0.38268343236508977173f;
    // T[b][r1] = e^{+i pi b r1 / 8}
    const float Tr[4][4] = {{1,1,1,1},
                            {1, C8,  CQ,  S8},
                            {1, CQ, 0.0f, -CQ},
                            {1, S8, -CQ, -C8}};
    const float Ti[4][4] = {{0,0,0,0},
                            {0, S8,  CQ,  C8},
                            {0, CQ, 1.0f,  CQ},
                            {0, C8,  CQ, -S8}};

    #pragma unroll
    for (int r1 = 0; r1 < 4; ++r1) {
        float zr[4], zi[4];
        #pragma unroll
        for (int b = 0; b < 4; ++b)
            cmulf(zr[b], zi[b], sr[4*r1+b], si[4*r1+b], Tr[b][r1], Ti[b][r1]);
        float u0r=zr[0]+zr[2], u0i=zi[0]+zi[2];
        float u1r=zr[0]-zr[2], u1i=zi[0]-zi[2];
        float u2r=zr[1]+zr[3], u2i=zi[1]+zi[3];
        float u3r=zr[1]-zr[3], u3i=zi[1]-zi[3];
        yr[r1]    = u0r+u2r; yi[r1]    = u0i+u2i;
        yr[r1+4]  = u1r-u3i; yi[r1+4]  = u1i+u3r;
        yr[r1+8]  = u0r-u2r; yi[r1+8]  = u0i-u2i;
        yr[r1+12] = u1r+u3i; yi[r1+12] = u1i-u3r;
    }
}

// Store 16 outputs with twiddles c_r = c0 * w1^r via a depth<=4 c-tree
// (3 squarings + 15 independent cmuls; register-only).
__device__ __forceinline__ void store16c(float2* d,
                                         const float* yr, const float* yi,
                                         int o, int m,
                                         float c0r, float c0i,
                                         float w1r, float w1i)
{
    float w2r = w1r*w1r - w1i*w1i, w2i = 2.0f*w1r*w1i;
    float w4r = w2r*w2r - w2i*w2i, w4i = 2.0f*w2r*w2i;
    float w8r = w4r*w4r - w4i*w4i, w8i = 2.0f*w4r*w4i;

    float cr[16], ci[16];
    cr[0] = c0r; ci[0] = c0i;
    cmulf(cr[1], ci[1], cr[0], ci[0], w1r, w1i);
    cmulf(cr[2], ci[2], cr[0], ci[0], w2r, w2i);
    cmulf(cr[3], ci[3], cr[1], ci[1], w2r, w2i);
    #pragma unroll
    for (int r = 4; r < 8; ++r)  cmulf(cr[r], ci[r], cr[r-4], ci[r-4], w4r, w4i);
    #pragma unroll
    for (int r = 8; r < 16; ++r) cmulf(cr[r], ci[r], cr[r-8], ci[r-8], w8r, w8i);

    #pragma unroll
    for (int r = 0; r < 16; ++r)
        d[P16(o + r*m)] = make_float2(yr[r]*cr[r] - yi[r]*ci[r],
                                      yr[r]*ci[r] + yi[r]*cr[r]);
}

__global__ void __launch_bounds__(ITH, 2)
cwt_kernel(const float* __restrict__ wft, float* __restrict__ out, int S)
{
    float2* A  = (float2*)sm_;
    float2* Bb = A + INV_CP;

    const int tid = threadIdx.x;
    const int s = blockIdx.x % S, b = blockIdx.x / S;
    const float2* __restrict__ F = g_F + b * FROW;
    const float*  __restrict__ w = wft + (size_t)s * N_FWD;

    float2 fn = F[4096];
    float  gn = w[4096];
    float  nyr = fn.x * gn, nyi = fn.y * gn;

    // Hoisted, pass-invariant twiddle bases (2 sincospif per thread total).
    float sA, cA;                                   // A = e^{+2 pi i tid/8192}
    sincospif((float)tid * (1.0f / 4096.0f), &sA, &cA);
    float w1r = cA * cA - sA * sA;                  // stage-1 base = A^2
    float w1i = 2.0f * cA * sA;
    const int jm2 = tid & ~15;                      // stage-2 jm
    float s2s, s2c;                                 // e^{+2 pi i jm2/4096}
    sincospif((float)jm2 * (1.0f / 2048.0f), &s2s, &s2c);

    // B(q) = e^{+i pi q/16} constants for the pass-1 rotation
    const float BQr[16] = { 1.0f,  0.98078528f,  0.92387953f,  0.83146961f,
                            0.70710678f,  0.55557023f,  0.38268343f,  0.19509032f,
                            0.0f, -0.19509032f, -0.38268343f, -0.55557023f,
                           -0.70710678f, -0.83146961f, -0.92387953f, -0.98078528f };
    const float BQi[16] = { 0.0f,  0.19509032f,  0.38268343f,  0.55557023f,
                            0.70710678f,  0.83146961f,  0.92387953f,  0.98078528f,
                            1.0f,  0.98078528f,  0.92387953f,  0.83146961f,
                            0.70710678f,  0.55557023f,  0.38268343f,  0.19509032f };

    float ev[8];   // pass-0 log values (same thread & columns in pass 1)

    #pragma unroll
    for (int pass = 0; pass < 2; ++pass) {
        float xr[16], xi[16], yr[16], yi[16];

        // ---- stage 1 (m=1, jm=tid): fused global load + spectrum multiply.
        // Pass 1 rotation e^{+2 pi i k/8192} = A(tid) * B(q), A folded into c0.
        #pragma unroll
        for (int q = 0; q < 16; ++q) {
            int k = tid + q * 256;
            float2 f = F[k];
            float  g = w[k];
            float vr = f.x * g, vi = f.y * g;
            if (pass) {
                float br = BQr[q], bi = BQi[q];
                float r2 = vr * br - vi * bi;
                float i2 = vr * bi + vi * br;
                vr = r2; vi = i2;
            }
            xr[q] = vr; xi[q] = vi;
        }
        bfly16_inv(xr, xi, yr, yi);
        if (pass == 0) store16c(A, yr, yi, 16 * tid, 1, 1.0f, 0.0f, w1r, w1i);
        else           store16c(A, yr, yi, 16 * tid, 1, cA,   sA,   w1r, w1i);
        __syncthreads();

        // ---- stage 2 (m=16)
        #pragma unroll
        for (int q = 0; q < 16; ++q) {
            float2 v = A[P16(tid + q * 256)];
            xr[q] = v.x; xi[q] = v.y;
        }
        bfly16_inv(xr, xi, yr, yi);
        {
            int k2 = tid & 15;
            store16c(Bb, yr, yi, 16 * jm2 + k2, 16, 1.0f, 0.0f, s2c, s2s);
        }
        __syncthreads();

        // ---- stage 3 (m=256, jm=0, W=1): fused Nyquist + log|.| + output.
        // Thread tid produces u = tid + 256 r; needed u in [1024,3072) -> r=4..11.
        #pragma unroll
        for (int q = 0; q < 16; ++q) {
            float2 v = Bb[P16(tid + q * 256)];
            xr[q] = v.x; xi[q] = v.y;
        }
        bfly16_inv(xr, xi, yr, yi);

        float nr = pass ? -nyr : nyr;
        float ni = pass ? -nyi : nyi;
        if (pass == 0) {
            #pragma unroll
            for (int r = 4; r <= 11; ++r) {
                float a = yr[r] + nr, b2 = yi[r] + ni;
                ev[r - 4] = fmaf(0.5f, __logf(a * a + b2 * b2), LOG_OFF);
            }
        } else {
            float2* o2 = (float2*)(out + (size_t)blockIdx.x * T_LEN);
            #pragma unroll
            for (int r = 4; r <= 11; ++r) {
                float a = yr[r] + nr, b2 = yi[r] + ni;
                float lg = fmaf(0.5f, __logf(a * a + b2 * b2), LOG_OFF);
                o2[tid + 256 * (r - 4)] = make_float2(ev[r - 4], lg);
            }
        }
        // No extra barrier needed: next pass's stage-2 store to Bb is
        // already separated from this pass's stage-3 loads of Bb by the
        // barrier after the next stage-1 store.
    }
}

// ---------------------------------------------------------------------------
extern "C" void kernel_launch(void* const* d_in, const int* in_sizes, int n_in,
                              void* d_out, int out_size)
{
    const float* in  = (const float*)d_in[0];
    const float* wft = (const float*)d_in[1];
    float* out = (float*)d_out;

    const int B = in_sizes[0] / T_LEN;     // 64
    const int S = in_sizes[1] / N_FWD;     // 75

    const int fwd_smem = 4 * FWD_PAD * sizeof(float);      // 147456 B
    const int cwt_smem = 2 * INV_CP * sizeof(float2);      //  69632 B
    cudaFuncSetAttribute(fwd_fft_kernel,
                         cudaFuncAttributeMaxDynamicSharedMemorySize, fwd_smem);
    cudaFuncSetAttribute(cwt_kernel,
                         cudaFuncAttributeMaxDynamicSharedMemorySize, cwt_smem);

    fwd_fft_kernel<<<B, FTH, fwd_smem>>>(in);
    cwt_kernel<<<B * S, ITH, cwt_smem>>>(wft, out, S);
}